// round 7
// baseline (speedup 1.0000x reference)
#include <cuda_runtime.h>

// DWT2 (2x2 Haar) : x[16,64,256,256] f32 -> out[16,256,128,128] f32
//   out[n, i*64+c, y, x] from 2x2 block at x[n,c,2y:2y+2, 2x:2x+2]
// HAAR rows: i0:(+ + + +), i1:(+ + - -), i2:(+ - + -), i3:(+ - - +), all * 0.5
//
// R6: persistent grid-stride, unroll x2 with front-batched loads (MLP=4/thread),
//     32-bit shift/mask indexing. Request shape identical to R1
//     (LDG.128 pairs, 4x STG.64 default policy).

static constexpr int N  = 16;
static constexpr int C  = 64;
static constexpr int H  = 256;
static constexpr int W  = 256;
static constexpr int H2 = H / 2;   // 128
static constexpr int W2 = W / 2;   // 128

static constexpr int XGROUPS = W / 4;   // 64 float4-groups along W
static constexpr unsigned TOTAL = (unsigned)N * C * H2 * XGROUPS;  // 8,388,608
static constexpr int PLANE = H2 * W2;          // 16384
static constexpr int OUT_I_STRIDE = C * PLANE; // 1,048,576

static constexpr int BLOCKS  = 148 * 8;   // one resident wave (8 CTAs/SM at 256 thr)
static constexpr int THREADS = 256;
static constexpr unsigned STRIDE = (unsigned)BLOCKS * THREADS;  // 303,104

struct WorkItem {
    const float4* in0;   // row 2y
    const float4* in1;   // row 2y+1
    float2*       o;     // out base (band 0)
};

__device__ __forceinline__ WorkItem decode(unsigned idx, const float* x, float* out)
{
    // idx = (((n*C + c)*H2 + y)*XGROUPS + xg), all power-of-two dims
    unsigned xg = idx & 63u;           // XGROUPS-1
    unsigned y  = (idx >> 6) & 127u;   // H2-1
    unsigned nc = idx >> 13;           // n*C + c  (0..1023)

    unsigned in_off  = ((nc << 8) | (y << 1)) * (unsigned)W + (xg << 2);  // (nc*H + 2y)*W + 4xg
    unsigned n  = nc >> 6;
    unsigned c  = nc & 63u;
    unsigned out_off = ((n << 8) | c) * (unsigned)PLANE + (y << 7) + (xg << 1);

    WorkItem w;
    w.in0 = reinterpret_cast<const float4*>(x + in_off);
    w.in1 = reinterpret_cast<const float4*>(x + in_off + W);
    w.o   = reinterpret_cast<float2*>(out + out_off);
    return w;
}

__device__ __forceinline__ void haar_store(float4 r0, float4 r1, float2* o)
{
    float ab0p = r0.x + r0.y, ab0m = r0.x - r0.y;
    float cd0p = r1.x + r1.y, cd0m = r1.x - r1.y;
    float ab1p = r0.z + r0.w, ab1m = r0.z - r0.w;
    float cd1p = r1.z + r1.w, cd1m = r1.z - r1.w;

    float2 o0 = make_float2(0.5f * (ab0p + cd0p), 0.5f * (ab1p + cd1p)); // LL
    float2 o1 = make_float2(0.5f * (ab0p - cd0p), 0.5f * (ab1p - cd1p));
    float2 o2 = make_float2(0.5f * (ab0m + cd0m), 0.5f * (ab1m + cd1m));
    float2 o3 = make_float2(0.5f * (ab0m - cd0m), 0.5f * (ab1m - cd1m));

    o[0]                          = o0;
    o[(unsigned)OUT_I_STRIDE / 2] = o1;   // float2 units
    o[(unsigned)OUT_I_STRIDE]     = o2;
    o[(unsigned)(3 * (OUT_I_STRIDE / 2))] = o3;
}

__global__ __launch_bounds__(THREADS) void dwt2_haar_kernel(
    const float* __restrict__ x, float* __restrict__ out)
{
    unsigned tid = blockIdx.x * (unsigned)THREADS + threadIdx.x;

    // TOTAL / STRIDE = 27.67 -> 27 full double-iterations of 2*STRIDE? Handle generally:
    unsigned i = tid;
    // main unrolled-x2 loop: front-batch 4 loads
    for (; i + STRIDE < TOTAL; i += 2 * STRIDE) {
        WorkItem w0 = decode(i,          x, out);
        WorkItem w1 = decode(i + STRIDE, x, out);

        float4 a0 = *w0.in0;
        float4 a1 = *w0.in1;
        float4 b0 = *w1.in0;
        float4 b1 = *w1.in1;

        haar_store(a0, a1, w0.o);
        haar_store(b0, b1, w1.o);
    }
    // tail (at most one item per thread)
    if (i < TOTAL) {
        WorkItem w = decode(i, x, out);
        float4 a0 = *w.in0;
        float4 a1 = *w.in1;
        haar_store(a0, a1, w.o);
    }
}

extern "C" void kernel_launch(void* const* d_in, const int* in_sizes, int n_in,
                              void* d_out, int out_size)
{
    const float* x = (const float*)d_in[0];
    float* out = (float*)d_out;
    dwt2_haar_kernel<<<BLOCKS, THREADS>>>(x, out);
}

// round 13
// speedup vs baseline: 1.1163x; 1.1163x over previous
#include <cuda_runtime.h>

// DWT2 (2x2 Haar) : x[16,64,256,256] f32 -> out[16,256,128,128] f32
//   out[n, i*64+c, y, x] from 2x2 block at x[n,c,2y:2y+2, 2x:2x+2]
// HAAR rows: i0:(+ + + +), i1:(+ + - -), i2:(+ - + -), i3:(+ - - +), all * 0.5
//
// Final shape = R1 (best measured: 73.9us kernel, 82.6% DRAM, 6544 GB/s).
// Per-thread: 2x LDG.128 (rows 2y, 2y+1), 4x STG.64 (one per Haar band),
// default cache policy, dense one-shot grid (32768 x 256).

static constexpr int N  = 16;
static constexpr int C  = 64;
static constexpr int H  = 256;
static constexpr int W  = 256;
static constexpr int H2 = H / 2;   // 128
static constexpr int W2 = W / 2;   // 128

static constexpr int XGROUPS = W / 4;                 // 64
static constexpr long long TOTAL = (long long)N * C * H2 * XGROUPS;  // 8,388,608
static constexpr int PLANE = H2 * W2;                 // 16384
static constexpr int OUT_I_STRIDE = C * PLANE;        // 1,048,576

__global__ __launch_bounds__(256) void dwt2_haar_kernel(
    const float* __restrict__ x, float* __restrict__ out)
{
    long long idx = (long long)blockIdx.x * blockDim.x + threadIdx.x;
    if (idx >= TOTAL) return;

    int xg = (int)(idx % XGROUPS);              // which float4 group along W
    int y  = (int)((idx / XGROUPS) % H2);       // output row
    int c  = (int)((idx / ((long long)XGROUPS * H2)) % C);
    int n  = (int)( idx / ((long long)XGROUPS * H2 * C));

    // input: rows 2y and 2y+1, columns [4*xg, 4*xg+3]
    const float* row0 = x + (((long long)(n * C + c) * H + 2 * y) * W + 4 * xg);
    const float* row1 = row0 + W;

    float4 r0 = *reinterpret_cast<const float4*>(row0);
    float4 r1 = *reinterpret_cast<const float4*>(row1);

    // two output pixels: (a,b / c,d) pairs
    float a0 = r0.x, b0 = r0.y, a1 = r0.z, b1 = r0.w;
    float c0 = r1.x, d0 = r1.y, c1 = r1.z, d1 = r1.w;

    // butterfly (save adds): sum/diff stages
    float ab0p = a0 + b0, ab0m = a0 - b0;
    float cd0p = c0 + d0, cd0m = c0 - d0;
    float ab1p = a1 + b1, ab1m = a1 - b1;
    float cd1p = c1 + d1, cd1m = c1 - d1;

    float2 o0 = make_float2(0.5f * (ab0p + cd0p), 0.5f * (ab1p + cd1p)); // LL
    float2 o1 = make_float2(0.5f * (ab0p - cd0p), 0.5f * (ab1p - cd1p)); // i=1
    float2 o2 = make_float2(0.5f * (ab0m + cd0m), 0.5f * (ab1m + cd1m)); // i=2
    float2 o3 = make_float2(0.5f * (ab0m - cd0m), 0.5f * (ab1m - cd1m)); // i=3

    // out[n, i*C + c, y, 2*xg .. 2*xg+1]
    long long obase = ((long long)n * 4 * C + c) * PLANE + (long long)y * W2 + 2 * xg;
    float* o = out + obase;
    *reinterpret_cast<float2*>(o)                    = o0;
    *reinterpret_cast<float2*>(o + 1 * OUT_I_STRIDE) = o1;
    *reinterpret_cast<float2*>(o + 2 * OUT_I_STRIDE) = o2;
    *reinterpret_cast<float2*>(o + 3 * OUT_I_STRIDE) = o3;
}

extern "C" void kernel_launch(void* const* d_in, const int* in_sizes, int n_in,
                              void* d_out, int out_size)
{
    const float* x = (const float*)d_in[0];
    float* out = (float*)d_out;

    const int threads = 256;
    const long long blocks = (TOTAL + threads - 1) / threads;  // 32768
    dwt2_haar_kernel<<<(unsigned)blocks, threads>>>(x, out);
}